// round 1
// baseline (speedup 1.0000x reference)
#include <cuda_runtime.h>

// Problem constants (shapes are fixed by the dataset).
#define N_ATOMS_C 20000
#define CAP 96          // per-atom bucket capacity; Poisson(32) => overflow ~never
#define OVF_CAP 8192
#define MP_SCALING 0.1f

// Scratch: __device__ globals (no allocations allowed anywhere).
__device__ int  g_count[N_ATOMS_C];
__device__ int2 g_bucket[N_ATOMS_C * CAP];   // (edge_id, neighbor_id)
__device__ int  g_ovf_count;
__device__ int  g_ovf[OVF_CAP];

__global__ void zero_kernel(int n_atoms) {
    int i = blockIdx.x * blockDim.x + threadIdx.x;
    if (i < n_atoms) g_count[i] = 0;
    if (i == 0) g_ovf_count = 0;
}

__global__ void scatter_kernel(const int* __restrict__ centers,
                               const int* __restrict__ neighbors, int E) {
    int e = blockIdx.x * blockDim.x + threadIdx.x;
    if (e >= E) return;
    int c = centers[e];
    int pos = atomicAdd(&g_count[c], 1);
    if (pos < CAP) {
        g_bucket[c * CAP + pos] = make_int2(e, neighbors[e]);
    } else {
        int o = atomicAdd(&g_ovf_count, 1);
        if (o < OVF_CAP) g_ovf[o] = e;
    }
}

// One warp handles one l-channel of one atom. lane = k (0..31).
// rb row slice for this l is a single coalesced 128B load; emb row likewise
// (L2-resident: 2.5MB working set). sh values for this l are loaded by the
// first (2l+1) lanes and broadcast via shfl.
template <int L>
__device__ __forceinline__ void accum_warp(
    int a, int deg, int k,
    const float* __restrict__ sh,
    const float* __restrict__ rb,
    const float* __restrict__ emb,
    float* __restrict__ out)
{
    constexpr int NM = 2 * L + 1;
    constexpr int M0 = L * L;
    float acc[NM];
#pragma unroll
    for (int j = 0; j < NM; j++) acc[j] = 0.0f;

    const int2* bk = g_bucket + (size_t)a * CAP;
    for (int i = 0; i < deg; i++) {
        int2 en = __ldg(bk + i);                                   // (e, n)
        float r   = __ldg(rb  + (size_t)en.x * 128 + L * 32 + k);  // rb[e, L, k]
        float em  = __ldg(emb + (size_t)en.y * 32  + k);           // emb[n, k]
        float t   = r * em;
        float shv = (k < NM) ? __ldg(sh + (size_t)en.x * 16 + M0 + k) : 0.0f;
#pragma unroll
        for (int j = 0; j < NM; j++)
            acc[j] = fmaf(__shfl_sync(0xffffffffu, shv, j), t, acc[j]);
    }

    float* o = out + (size_t)a * 512 + M0 * 32 + k;
#pragma unroll
    for (int j = 0; j < NM; j++) o[j * 32] = acc[j] * MP_SCALING;
}

__global__ __launch_bounds__(128) void gather_kernel(
    const float* __restrict__ sh, const float* __restrict__ rb,
    const float* __restrict__ emb, float* __restrict__ out)
{
    int a = blockIdx.x;
    int w = threadIdx.x >> 5;
    int k = threadIdx.x & 31;
    int deg = g_count[a];
    if (deg > CAP) deg = CAP;
    switch (w) {
        case 0: accum_warp<0>(a, deg, k, sh, rb, emb, out); break;
        case 1: accum_warp<1>(a, deg, k, sh, rb, emb, out); break;
        case 2: accum_warp<2>(a, deg, k, sh, rb, emb, out); break;
        case 3: accum_warp<3>(a, deg, k, sh, rb, emb, out); break;
    }
}

// Correctness fallback for bucket overflow (statistically never executes).
__global__ void overflow_kernel(
    const float* __restrict__ sh, const float* __restrict__ rb,
    const float* __restrict__ emb,
    const int* __restrict__ centers, const int* __restrict__ neighbors,
    float* __restrict__ out)
{
    int novf = g_ovf_count;
    if (novf > OVF_CAP) novf = OVF_CAP;
    int m = threadIdx.x >> 5;   // 512 threads: m = 0..15
    int k = threadIdx.x & 31;
    int l = (m >= 9) ? 3 : (m >= 4) ? 2 : (m >= 1) ? 1 : 0;
    for (int i = blockIdx.x; i < novf; i += gridDim.x) {
        int e = g_ovf[i];
        int c = centers[e];
        int n = neighbors[e];
        float v = MP_SCALING
                * __ldg(sh  + (size_t)e * 16  + m)
                * __ldg(rb  + (size_t)e * 128 + l * 32 + k)
                * __ldg(emb + (size_t)n * 32  + k);
        atomicAdd(out + (size_t)c * 512 + m * 32 + k, v);
    }
}

extern "C" void kernel_launch(void* const* d_in, const int* in_sizes, int n_in,
                              void* d_out, int out_size) {
    const float* sh        = (const float*)d_in[0];  // (E, 16)
    const float* rb        = (const float*)d_in[1];  // (E, 4, 32)
    const float* emb       = (const float*)d_in[2];  // (n_atoms, 32)
    const int*   centers   = (const int*)d_in[3];    // (E,)
    const int*   neighbors = (const int*)d_in[4];    // (E,)
    float*       out       = (float*)d_out;          // (n_atoms, 16, 32)

    int E       = in_sizes[0] / 16;
    int n_atoms = in_sizes[2] / 32;

    zero_kernel<<<(n_atoms + 255) / 256, 256>>>(n_atoms);
    scatter_kernel<<<(E + 255) / 256, 256>>>(centers, neighbors, E);
    gather_kernel<<<n_atoms, 128>>>(sh, rb, emb, out);
    overflow_kernel<<<8, 512>>>(sh, rb, emb, centers, neighbors, out);
}

// round 3
// speedup vs baseline: 1.2078x; 1.2078x over previous
#include <cuda_runtime.h>

// Problem constants (shapes are fixed by the dataset).
#define N_ATOMS_C 20000
#define CAP 96          // per-atom bucket capacity; Poisson(32) => overflow ~never
#define OVF_CAP 8192
#define MP_SCALING 0.1f

// Scratch: __device__ globals (no allocations allowed anywhere).
__device__ int  g_count[N_ATOMS_C];
__device__ int2 g_bucket[N_ATOMS_C * CAP];   // (edge_id, neighbor_id)
__device__ int  g_ovf_count;
__device__ int  g_ovf[OVF_CAP];

__global__ void zero_kernel(int n_atoms) {
    int i = blockIdx.x * blockDim.x + threadIdx.x;
    if (i < n_atoms) g_count[i] = 0;
    if (i == 0) g_ovf_count = 0;
}

__global__ void scatter_kernel(const int* __restrict__ centers,
                               const int* __restrict__ neighbors, int E) {
    int e = blockIdx.x * blockDim.x + threadIdx.x;
    if (e >= E) return;
    int c = centers[e];
    int pos = atomicAdd(&g_count[c], 1);
    if (pos < CAP) {
        g_bucket[c * CAP + pos] = make_int2(e, neighbors[e]);
    } else {
        int o = atomicAdd(&g_ovf_count, 1);
        if (o < OVF_CAP) g_ovf[o] = e;
    }
}

// One warp handles one l-channel of one atom. lane = k (0..31).
// Inner loop unrolled x4 with a batched load phase: all 10+ LDGs of the
// 4-edge group are issued before any dependent math -> MLP ~8 per warp,
// hiding the ~577-cycle DRAM latency of the random rb row reads.
template <int L>
__device__ __forceinline__ void accum_warp(
    int a, int deg, int k,
    const float* __restrict__ sh,
    const float* __restrict__ rb,
    const float* __restrict__ emb,
    float* __restrict__ out)
{
    constexpr int NM = 2 * L + 1;
    constexpr int M0 = L * L;
    float acc[NM];
#pragma unroll
    for (int j = 0; j < NM; j++) acc[j] = 0.0f;

    const int2* bk = g_bucket + (size_t)a * CAP;

    int i = 0;
    for (; i + 4 <= deg; i += 4) {
        // ---- load phase (independent LDGs, front-batched) ----
        int4 b01 = __ldg((const int4*)(bk + i));      // e0,n0,e1,n1
        int4 b23 = __ldg((const int4*)(bk + i + 2));  // e2,n2,e3,n3

        float r0 = __ldg(rb + (size_t)b01.x * 128 + L * 32 + k);
        float r1 = __ldg(rb + (size_t)b01.z * 128 + L * 32 + k);
        float r2 = __ldg(rb + (size_t)b23.x * 128 + L * 32 + k);
        float r3 = __ldg(rb + (size_t)b23.z * 128 + L * 32 + k);

        float e0 = __ldg(emb + (size_t)b01.y * 32 + k);
        float e1 = __ldg(emb + (size_t)b01.w * 32 + k);
        float e2 = __ldg(emb + (size_t)b23.y * 32 + k);
        float e3 = __ldg(emb + (size_t)b23.w * 32 + k);

        float s0 = 0.f, s1 = 0.f, s2 = 0.f, s3 = 0.f;
        if (k < NM) {
            s0 = __ldg(sh + (size_t)b01.x * 16 + M0 + k);
            s1 = __ldg(sh + (size_t)b01.z * 16 + M0 + k);
            s2 = __ldg(sh + (size_t)b23.x * 16 + M0 + k);
            s3 = __ldg(sh + (size_t)b23.z * 16 + M0 + k);
        }

        // ---- compute phase ----
        float t0 = r0 * e0, t1 = r1 * e1, t2 = r2 * e2, t3 = r3 * e3;
#pragma unroll
        for (int j = 0; j < NM; j++) {
            acc[j] = fmaf(__shfl_sync(0xffffffffu, s0, j), t0, acc[j]);
            acc[j] = fmaf(__shfl_sync(0xffffffffu, s1, j), t1, acc[j]);
            acc[j] = fmaf(__shfl_sync(0xffffffffu, s2, j), t2, acc[j]);
            acc[j] = fmaf(__shfl_sync(0xffffffffu, s3, j), t3, acc[j]);
        }
    }
    // tail
    for (; i < deg; i++) {
        int2 en = __ldg(bk + i);
        float r  = __ldg(rb  + (size_t)en.x * 128 + L * 32 + k);
        float em = __ldg(emb + (size_t)en.y * 32  + k);
        float t  = r * em;
        float sv = (k < NM) ? __ldg(sh + (size_t)en.x * 16 + M0 + k) : 0.0f;
#pragma unroll
        for (int j = 0; j < NM; j++)
            acc[j] = fmaf(__shfl_sync(0xffffffffu, sv, j), t, acc[j]);
    }

    float* o = out + (size_t)a * 512 + M0 * 32 + k;
#pragma unroll
    for (int j = 0; j < NM; j++) o[j * 32] = acc[j] * MP_SCALING;
}

__global__ __launch_bounds__(128) void gather_kernel(
    const float* __restrict__ sh, const float* __restrict__ rb,
    const float* __restrict__ emb, float* __restrict__ out)
{
    int a = blockIdx.x;
    int w = threadIdx.x >> 5;
    int k = threadIdx.x & 31;
    int deg = g_count[a];
    if (deg > CAP) deg = CAP;
    switch (w) {
        case 0: accum_warp<0>(a, deg, k, sh, rb, emb, out); break;
        case 1: accum_warp<1>(a, deg, k, sh, rb, emb, out); break;
        case 2: accum_warp<2>(a, deg, k, sh, rb, emb, out); break;
        case 3: accum_warp<3>(a, deg, k, sh, rb, emb, out); break;
    }
}

// Correctness fallback for bucket overflow (statistically never executes).
__global__ void overflow_kernel(
    const float* __restrict__ sh, const float* __restrict__ rb,
    const float* __restrict__ emb,
    const int* __restrict__ centers, const int* __restrict__ neighbors,
    float* __restrict__ out)
{
    int novf = g_ovf_count;
    if (novf > OVF_CAP) novf = OVF_CAP;
    int m = threadIdx.x >> 5;   // 512 threads: m = 0..15
    int k = threadIdx.x & 31;
    int l = (m >= 9) ? 3 : (m >= 4) ? 2 : (m >= 1) ? 1 : 0;
    for (int i = blockIdx.x; i < novf; i += gridDim.x) {
        int e = g_ovf[i];
        int c = centers[e];
        int n = neighbors[e];
        float v = MP_SCALING
                * __ldg(sh  + (size_t)e * 16  + m)
                * __ldg(rb  + (size_t)e * 128 + l * 32 + k)
                * __ldg(emb + (size_t)n * 32  + k);
        atomicAdd(out + (size_t)c * 512 + m * 32 + k, v);
    }
}

extern "C" void kernel_launch(void* const* d_in, const int* in_sizes, int n_in,
                              void* d_out, int out_size) {
    const float* sh        = (const float*)d_in[0];  // (E, 16)
    const float* rb        = (const float*)d_in[1];  // (E, 4, 32)
    const float* emb       = (const float*)d_in[2];  // (n_atoms, 32)
    const int*   centers   = (const int*)d_in[3];    // (E,)
    const int*   neighbors = (const int*)d_in[4];    // (E,)
    float*       out       = (float*)d_out;          // (n_atoms, 16, 32)

    int E       = in_sizes[0] / 16;
    int n_atoms = in_sizes[2] / 32;

    zero_kernel<<<(n_atoms + 255) / 256, 256>>>(n_atoms);
    scatter_kernel<<<(E + 255) / 256, 256>>>(centers, neighbors, E);
    gather_kernel<<<n_atoms, 128>>>(sh, rb, emb, out);
    overflow_kernel<<<8, 512>>>(sh, rb, emb, centers, neighbors, out);
}

// round 4
// speedup vs baseline: 1.5894x; 1.3160x over previous
#include <cuda_runtime.h>

// Problem constants (shapes are fixed by the dataset).
#define N_ATOMS_C 20000
#define CAP 96          // per-atom bucket capacity; Poisson(32) => overflow ~never
#define OVF_CAP 8192
#define MP_SCALING 0.1f

// Scratch: __device__ globals (no allocations allowed anywhere).
__device__ int  g_count[N_ATOMS_C];
__device__ int2 g_bucket[N_ATOMS_C * CAP];   // (edge_id, neighbor_id)
__device__ int  g_ovf_count;
__device__ int  g_ovf[OVF_CAP];

__global__ void zero_kernel(int n_atoms) {
    int i = blockIdx.x * blockDim.x + threadIdx.x;
    if (i < n_atoms) g_count[i] = 0;
    if (i == 0) g_ovf_count = 0;
}

__global__ void scatter_kernel(const int* __restrict__ centers,
                               const int* __restrict__ neighbors, int E) {
    int e = blockIdx.x * blockDim.x + threadIdx.x;
    if (e >= E) return;
    int c = centers[e];
    int pos = atomicAdd(&g_count[c], 1);
    if (pos < CAP) {
        g_bucket[c * CAP + pos] = make_int2(e, neighbors[e]);
    } else {
        int o = atomicAdd(&g_ovf_count, 1);
        if (o < OVF_CAP) g_ovf[o] = e;
    }
}

// Per-edge accumulate into acc[16]. All selects resolve at compile time.
__device__ __forceinline__ void edge_accum(
    float acc[16], int k,
    const float* __restrict__ sh,
    const float* __restrict__ rb,
    const float* __restrict__ emb,
    int e, int n)
{
    const float* rbe = rb + (size_t)e * 128 + k;
    float r0 = __ldg(rbe);          // rb[e,0,k]
    float r1 = __ldg(rbe + 32);     // rb[e,1,k]
    float r2 = __ldg(rbe + 64);     // rb[e,2,k]
    float r3 = __ldg(rbe + 96);     // rb[e,3,k]
    float em = __ldg(emb + (size_t)n * 32 + k);
    float sv = (k < 16) ? __ldg(sh + (size_t)e * 16 + k) : 0.0f;

    float t0 = r0 * em, t1 = r1 * em, t2 = r2 * em, t3 = r3 * em;
#pragma unroll
    for (int m = 0; m < 16; m++) {
        float s = __shfl_sync(0xffffffffu, sv, m);
        float t = (m < 1) ? t0 : (m < 4) ? t1 : (m < 9) ? t2 : t3;
        acc[m] = fmaf(s, t, acc[m]);
    }
}

// One warp per atom; lane = k. Per edge: 4 rb + 1 emb + 1 sh + 0.5 bucket
// LDG instructions (6.5/edge chip-wide vs 14/edge in the 4-warp scheme),
// so the LSU issue floor (~26us) sits well under the DRAM floor (~65us).
// x2 edge unroll front-batches 13 LDGs per iteration for MLP.
__global__ __launch_bounds__(256) void gather_kernel(
    const float* __restrict__ sh, const float* __restrict__ rb,
    const float* __restrict__ emb, float* __restrict__ out,
    int n_atoms)
{
    int a = blockIdx.x * 8 + (threadIdx.x >> 5);
    if (a >= n_atoms) return;
    int k = threadIdx.x & 31;

    int deg = g_count[a];
    if (deg > CAP) deg = CAP;

    float acc[16];
#pragma unroll
    for (int m = 0; m < 16; m++) acc[m] = 0.0f;

    const int2* bk = g_bucket + (size_t)a * CAP;

    int i = 0;
    for (; i + 2 <= deg; i += 2) {
        int4 b = __ldg((const int4*)(bk + i));   // e0,n0,e1,n1

        // ---- front-batched load phase for both edges ----
        const float* rb0 = rb + (size_t)b.x * 128 + k;
        float a0 = __ldg(rb0), a1 = __ldg(rb0 + 32), a2 = __ldg(rb0 + 64), a3 = __ldg(rb0 + 96);
        const float* rb1 = rb + (size_t)b.z * 128 + k;
        float c0 = __ldg(rb1), c1 = __ldg(rb1 + 32), c2 = __ldg(rb1 + 64), c3 = __ldg(rb1 + 96);
        float em0 = __ldg(emb + (size_t)b.y * 32 + k);
        float em1 = __ldg(emb + (size_t)b.w * 32 + k);
        float sv0 = (k < 16) ? __ldg(sh + (size_t)b.x * 16 + k) : 0.0f;
        float sv1 = (k < 16) ? __ldg(sh + (size_t)b.z * 16 + k) : 0.0f;

        // ---- compute phase ----
        float t00 = a0 * em0, t01 = a1 * em0, t02 = a2 * em0, t03 = a3 * em0;
        float t10 = c0 * em1, t11 = c1 * em1, t12 = c2 * em1, t13 = c3 * em1;
#pragma unroll
        for (int m = 0; m < 16; m++) {
            float s0 = __shfl_sync(0xffffffffu, sv0, m);
            float s1 = __shfl_sync(0xffffffffu, sv1, m);
            float u0 = (m < 1) ? t00 : (m < 4) ? t01 : (m < 9) ? t02 : t03;
            float u1 = (m < 1) ? t10 : (m < 4) ? t11 : (m < 9) ? t12 : t13;
            acc[m] = fmaf(s0, u0, acc[m]);
            acc[m] = fmaf(s1, u1, acc[m]);
        }
    }
    if (i < deg) {
        int2 en = __ldg(bk + i);
        edge_accum(acc, k, sh, rb, emb, en.x, en.y);
    }

    float* o = out + (size_t)a * 512 + k;
#pragma unroll
    for (int m = 0; m < 16; m++) o[m * 32] = acc[m] * MP_SCALING;
}

// Correctness fallback for bucket overflow (statistically never executes).
__global__ void overflow_kernel(
    const float* __restrict__ sh, const float* __restrict__ rb,
    const float* __restrict__ emb,
    const int* __restrict__ centers, const int* __restrict__ neighbors,
    float* __restrict__ out)
{
    int novf = g_ovf_count;
    if (novf > OVF_CAP) novf = OVF_CAP;
    int m = threadIdx.x >> 5;   // 512 threads: m = 0..15
    int k = threadIdx.x & 31;
    int l = (m >= 9) ? 3 : (m >= 4) ? 2 : (m >= 1) ? 1 : 0;
    for (int i = blockIdx.x; i < novf; i += gridDim.x) {
        int e = g_ovf[i];
        int c = centers[e];
        int n = neighbors[e];
        float v = MP_SCALING
                * __ldg(sh  + (size_t)e * 16  + m)
                * __ldg(rb  + (size_t)e * 128 + l * 32 + k)
                * __ldg(emb + (size_t)n * 32  + k);
        atomicAdd(out + (size_t)c * 512 + m * 32 + k, v);
    }
}

extern "C" void kernel_launch(void* const* d_in, const int* in_sizes, int n_in,
                              void* d_out, int out_size) {
    const float* sh        = (const float*)d_in[0];  // (E, 16)
    const float* rb        = (const float*)d_in[1];  // (E, 4, 32)
    const float* emb       = (const float*)d_in[2];  // (n_atoms, 32)
    const int*   centers   = (const int*)d_in[3];    // (E,)
    const int*   neighbors = (const int*)d_in[4];    // (E,)
    float*       out       = (float*)d_out;          // (n_atoms, 16, 32)

    int E       = in_sizes[0] / 16;
    int n_atoms = in_sizes[2] / 32;

    zero_kernel<<<(n_atoms + 255) / 256, 256>>>(n_atoms);
    scatter_kernel<<<(E + 255) / 256, 256>>>(centers, neighbors, E);
    gather_kernel<<<(n_atoms + 7) / 8, 256>>>(sh, rb, emb, out, n_atoms);
    overflow_kernel<<<8, 512>>>(sh, rb, emb, centers, neighbors, out);
}

// round 5
// speedup vs baseline: 1.7174x; 1.0805x over previous
#include <cuda_runtime.h>

// Problem constants (shapes are fixed by the dataset).
#define N_ATOMS_C 20000
#define CAP 96          // per-atom bucket capacity; dataset max degree ~60
#define OVF_CAP 8192
#define MP_SCALING 0.1f

// Scratch: __device__ globals (no allocations allowed; zero-initialized at
// module load). Invariant: g_count/g_ovf_count are 0 on entry to
// kernel_launch and restored to 0 by gather_kernel, so every call does
// identical work.
__device__ int  g_count[N_ATOMS_C];
__device__ int2 g_bucket[N_ATOMS_C * CAP];   // (edge_id, neighbor_id)
__device__ int  g_ovf_count;
__device__ int  g_ovf[OVF_CAP];

__device__ __forceinline__ void scatter_one(int e, int c, int n) {
    int pos = atomicAdd(&g_count[c], 1);
    if (pos < CAP) {
        g_bucket[c * CAP + pos] = make_int2(e, n);
    } else {
        int o = atomicAdd(&g_ovf_count, 1);
        if (o < OVF_CAP) g_ovf[o] = e;
    }
}

__global__ void scatter_kernel(const int* __restrict__ centers,
                               const int* __restrict__ neighbors, int E) {
    int t = blockIdx.x * blockDim.x + threadIdx.x;
    int e = t * 2;
    if (e + 1 < E) {
        int2 c = *(const int2*)(centers + e);
        int2 n = *(const int2*)(neighbors + e);
        scatter_one(e,     c.x, n.x);
        scatter_one(e + 1, c.y, n.y);
    } else if (e < E) {
        scatter_one(e, centers[e], neighbors[e]);
    }
}

// Single-edge accumulate (tail / overflow path).
__device__ __forceinline__ void edge_accum(
    float acc[16], int k,
    const float* __restrict__ sh,
    const float* __restrict__ rb,
    const float* __restrict__ emb,
    int e, int n)
{
    const float* rbe = rb + (size_t)e * 128 + k;
    float r0 = __ldg(rbe), r1 = __ldg(rbe + 32), r2 = __ldg(rbe + 64), r3 = __ldg(rbe + 96);
    float em = __ldg(emb + (size_t)n * 32 + k);
    float sv = (k < 16) ? __ldg(sh + (size_t)e * 16 + k) : 0.0f;
    float t0 = r0 * em, t1 = r1 * em, t2 = r2 * em, t3 = r3 * em;
#pragma unroll
    for (int m = 0; m < 16; m++) {
        float s = __shfl_sync(0xffffffffu, sv, m);
        float t = (m < 1) ? t0 : (m < 4) ? t1 : (m < 9) ? t2 : t3;
        acc[m] = fmaf(s, t, acc[m]);
    }
}

// One warp per atom; lane = k. x4 edge unroll front-batches 24 LDGs/iter.
// sh rows for two edges are loaded by one LDG (lanes 0-15 edge A, 16-31
// edge B) and distributed via shfl lanes m / m+16.
// Also absorbs overflow handling and scratch reset (saves 2 launches).
__global__ __launch_bounds__(256) void gather_kernel(
    const float* __restrict__ sh, const float* __restrict__ rb,
    const float* __restrict__ emb,
    const int* __restrict__ centers, const int* __restrict__ neighbors,
    float* __restrict__ out, int n_atoms)
{
    int a = blockIdx.x * 8 + (threadIdx.x >> 5);
    if (a >= n_atoms) return;
    int k = threadIdx.x & 31;

    int deg_raw = g_count[a];
    int deg = deg_raw > CAP ? CAP : deg_raw;
    int novf = 0;
    if (deg_raw > CAP) {           // statistically never on this dataset
        novf = g_ovf_count;
        if (novf > OVF_CAP) novf = OVF_CAP;
    }

    float acc[16];
#pragma unroll
    for (int m = 0; m < 16; m++) acc[m] = 0.0f;

    const int2* bk = g_bucket + (size_t)a * CAP;

    int i = 0;
    for (; i + 4 <= deg; i += 4) {
        int4 bA = __ldg((const int4*)(bk + i));      // e0,n0,e1,n1
        int4 bB = __ldg((const int4*)(bk + i + 2));  // e2,n2,e3,n3

        // ---- front-batched load phase ----
        const float* p0 = rb + (size_t)bA.x * 128 + k;
        const float* p1 = rb + (size_t)bA.z * 128 + k;
        const float* p2 = rb + (size_t)bB.x * 128 + k;
        const float* p3 = rb + (size_t)bB.z * 128 + k;
        float r00=__ldg(p0), r01=__ldg(p0+32), r02=__ldg(p0+64), r03=__ldg(p0+96);
        float r10=__ldg(p1), r11=__ldg(p1+32), r12=__ldg(p1+64), r13=__ldg(p1+96);
        float r20=__ldg(p2), r21=__ldg(p2+32), r22=__ldg(p2+64), r23=__ldg(p2+96);
        float r30=__ldg(p3), r31=__ldg(p3+32), r32=__ldg(p3+64), r33=__ldg(p3+96);
        float em0 = __ldg(emb + (size_t)bA.y * 32 + k);
        float em1 = __ldg(emb + (size_t)bA.w * 32 + k);
        float em2 = __ldg(emb + (size_t)bB.y * 32 + k);
        float em3 = __ldg(emb + (size_t)bB.w * 32 + k);
        float svA = __ldg(sh + ((k < 16) ? (size_t)bA.x * 16 + k
                                         : (size_t)bA.z * 16 + (k - 16)));
        float svB = __ldg(sh + ((k < 16) ? (size_t)bB.x * 16 + k
                                         : (size_t)bB.z * 16 + (k - 16)));

        // ---- compute phase ----
        float t00=r00*em0, t01=r01*em0, t02=r02*em0, t03=r03*em0;
        float t10=r10*em1, t11=r11*em1, t12=r12*em1, t13=r13*em1;
        float t20=r20*em2, t21=r21*em2, t22=r22*em2, t23=r23*em2;
        float t30=r30*em3, t31=r31*em3, t32=r32*em3, t33=r33*em3;
#pragma unroll
        for (int m = 0; m < 16; m++) {
            float s0 = __shfl_sync(0xffffffffu, svA, m);
            float s1 = __shfl_sync(0xffffffffu, svA, m + 16);
            float s2 = __shfl_sync(0xffffffffu, svB, m);
            float s3 = __shfl_sync(0xffffffffu, svB, m + 16);
            float u0 = (m < 1) ? t00 : (m < 4) ? t01 : (m < 9) ? t02 : t03;
            float u1 = (m < 1) ? t10 : (m < 4) ? t11 : (m < 9) ? t12 : t13;
            float u2 = (m < 1) ? t20 : (m < 4) ? t21 : (m < 9) ? t22 : t23;
            float u3 = (m < 1) ? t30 : (m < 4) ? t31 : (m < 9) ? t32 : t33;
            acc[m] = fmaf(s0, u0, acc[m]);
            acc[m] = fmaf(s1, u1, acc[m]);
            acc[m] = fmaf(s2, u2, acc[m]);
            acc[m] = fmaf(s3, u3, acc[m]);
        }
    }
    for (; i < deg; i++) {                       // tail (<=3 edges)
        int2 en = __ldg(bk + i);
        edge_accum(acc, k, sh, rb, emb, en.x, en.y);
    }

    // Overflow edges for this atom (novf==0 on this dataset).
    for (int j = 0; j < novf; j++) {
        int e = g_ovf[j];
        if (centers[e] == a) edge_accum(acc, k, sh, rb, emb, e, neighbors[e]);
    }

    float* o = out + (size_t)a * 512 + k;
#pragma unroll
    for (int m = 0; m < 16; m++) o[m * 32] = acc[m] * MP_SCALING;

    // Restore scratch invariant for the next graph replay.
    if (k == 0) g_count[a] = 0;
    if (a == 0 && k == 0) g_ovf_count = 0;
}

extern "C" void kernel_launch(void* const* d_in, const int* in_sizes, int n_in,
                              void* d_out, int out_size) {
    const float* sh        = (const float*)d_in[0];  // (E, 16)
    const float* rb        = (const float*)d_in[1];  // (E, 4, 32)
    const float* emb       = (const float*)d_in[2];  // (n_atoms, 32)
    const int*   centers   = (const int*)d_in[3];    // (E,)
    const int*   neighbors = (const int*)d_in[4];    // (E,)
    float*       out       = (float*)d_out;          // (n_atoms, 16, 32)

    int E       = in_sizes[0] / 16;
    int n_atoms = in_sizes[2] / 32;

    scatter_kernel<<<(E / 2 + 255) / 256, 256>>>(centers, neighbors, E);
    gather_kernel<<<(n_atoms + 7) / 8, 256>>>(sh, rb, emb, centers, neighbors,
                                              out, n_atoms);
}